// round 1
// baseline (speedup 1.0000x reference)
#include <cuda_runtime.h>
#include <cuda_bf16.h>
#include <math.h>

// ---------------------------------------------------------------------------
// GlobalInteractionModule: cross-community attention block, N=8192, D=1024.
//   Q=xWq+bq; K=xWk+bk; V=xWv+bv
//   S = (Q K^T) / sqrt(128), masked -inf where community_ids equal
//   P = softmax_rows(S);  O = P V;  H = O Wo + bo + x;  out = LayerNorm(H)
// ---------------------------------------------------------------------------

#define NTOK 8192
#define DIM  1024

// Scratch (static __device__ — no allocations allowed)
__device__ float g_Q[(size_t)NTOK * DIM];
__device__ float g_K[(size_t)NTOK * DIM];
__device__ float g_V[(size_t)NTOK * DIM];
__device__ float g_O[(size_t)NTOK * DIM];
__device__ float g_S[(size_t)NTOK * NTOK];   // 256 MB score/prob matrix

#define BM 128
#define BN 128
#define BK 16

// ---------------------------------------------------------------------------
// NN GEMM: C[M,N] = A[M,K] @ B[K,N] (+ bias[N]) (+ resid[M,N])
// 128x128x16 tiles, 256 threads, 8x8 microtile per thread.
// ---------------------------------------------------------------------------
__global__ __launch_bounds__(256)
void gemm_nn_kernel(const float* __restrict__ A, const float* __restrict__ B,
                    const float* __restrict__ bias, const float* __restrict__ resid,
                    float* __restrict__ C, int M, int N, int K)
{
    __shared__ float As[BK][BM + 1];
    __shared__ float Bs[BK][BN + 1];

    const int bm = blockIdx.y * BM;
    const int bn = blockIdx.x * BN;
    const int tid = threadIdx.x;
    const int tx = tid & 15;        // 0..15 -> column group
    const int ty = tid >> 4;        // 0..15 -> row group

    float acc[8][8];
#pragma unroll
    for (int i = 0; i < 8; i++)
#pragma unroll
        for (int j = 0; j < 8; j++) acc[i][j] = 0.f;

    for (int k0 = 0; k0 < K; k0 += BK) {
        // A tile: 128 rows x 16 cols. idx -> (r = idx/16, c = idx%16)
#pragma unroll
        for (int i = 0; i < 8; i++) {
            int idx = tid + i * 256;
            int r = idx >> 4, c = idx & 15;
            As[c][r] = A[(size_t)(bm + r) * K + k0 + c];
        }
        // B tile: 16 rows x 128 cols. idx -> (r = idx/128, c = idx%128)
#pragma unroll
        for (int i = 0; i < 8; i++) {
            int idx = tid + i * 256;
            int r = idx >> 7, c = idx & 127;
            Bs[r][c] = B[(size_t)(k0 + r) * N + bn + c];
        }
        __syncthreads();

#pragma unroll
        for (int kk = 0; kk < BK; kk++) {
            float a[8], b[8];
#pragma unroll
            for (int i = 0; i < 8; i++) a[i] = As[kk][ty * 8 + i];
#pragma unroll
            for (int j = 0; j < 8; j++) b[j] = Bs[kk][tx * 8 + j];
#pragma unroll
            for (int i = 0; i < 8; i++)
#pragma unroll
                for (int j = 0; j < 8; j++)
                    acc[i][j] = fmaf(a[i], b[j], acc[i][j]);
        }
        __syncthreads();
    }

#pragma unroll
    for (int i = 0; i < 8; i++) {
        int r = bm + ty * 8 + i;
#pragma unroll
        for (int j = 0; j < 8; j++) {
            int c = bn + tx * 8 + j;
            float v = acc[i][j];
            if (bias)  v += bias[c];
            if (resid) v += resid[(size_t)r * N + c];
            C[(size_t)r * N + c] = v;
        }
    }
}

// ---------------------------------------------------------------------------
// NT GEMM with community mask: S[N,N] = (Q[N,D] @ Kmat[N,D]^T) * scale,
// set to -1e30 where ids match.
// ---------------------------------------------------------------------------
__global__ __launch_bounds__(256)
void gemm_nt_mask_kernel(const float* __restrict__ Q, const float* __restrict__ Kmat,
                         const int* __restrict__ ids, float* __restrict__ S,
                         int N, int D, float scale)
{
    __shared__ float As[BK][BM + 1];
    __shared__ float Bs[BK][BN + 1];
    __shared__ int idsR[BM];
    __shared__ int idsC[BN];

    const int bm = blockIdx.y * BM;
    const int bn = blockIdx.x * BN;
    const int tid = threadIdx.x;
    const int tx = tid & 15;
    const int ty = tid >> 4;

    if (tid < 128)       idsR[tid]       = ids[bm + tid];
    else                 idsC[tid - 128] = ids[bn + tid - 128];

    float acc[8][8];
#pragma unroll
    for (int i = 0; i < 8; i++)
#pragma unroll
        for (int j = 0; j < 8; j++) acc[i][j] = 0.f;

    for (int k0 = 0; k0 < D; k0 += BK) {
        // Q tile: rows of Q
#pragma unroll
        for (int i = 0; i < 8; i++) {
            int idx = tid + i * 256;
            int r = idx >> 4, c = idx & 15;
            As[c][r] = Q[(size_t)(bm + r) * D + k0 + c];
        }
        // K tile (transposed use): Bs[k][n] = Kmat[bn+n][k0+k]
#pragma unroll
        for (int i = 0; i < 8; i++) {
            int idx = tid + i * 256;
            int n = idx >> 4, c = idx & 15;
            Bs[c][n] = Kmat[(size_t)(bn + n) * D + k0 + c];
        }
        __syncthreads();

#pragma unroll
        for (int kk = 0; kk < BK; kk++) {
            float a[8], b[8];
#pragma unroll
            for (int i = 0; i < 8; i++) a[i] = As[kk][ty * 8 + i];
#pragma unroll
            for (int j = 0; j < 8; j++) b[j] = Bs[kk][tx * 8 + j];
#pragma unroll
            for (int i = 0; i < 8; i++)
#pragma unroll
                for (int j = 0; j < 8; j++)
                    acc[i][j] = fmaf(a[i], b[j], acc[i][j]);
        }
        __syncthreads();
    }

#pragma unroll
    for (int i = 0; i < 8; i++) {
        int rl = ty * 8 + i;
        int r = bm + rl;
#pragma unroll
        for (int j = 0; j < 8; j++) {
            int cl = tx * 8 + j;
            int c = bn + cl;
            float v = (idsR[rl] == idsC[cl]) ? -1e30f : acc[i][j] * scale;
            S[(size_t)r * N + c] = v;
        }
    }
}

// ---------------------------------------------------------------------------
// Row softmax over N=8192, in-place. One block (256 thr) per row.
// ---------------------------------------------------------------------------
__device__ __forceinline__ float warpMax(float v) {
#pragma unroll
    for (int o = 16; o; o >>= 1) v = fmaxf(v, __shfl_xor_sync(0xFFFFFFFFu, v, o));
    return v;
}
__device__ __forceinline__ float warpSum(float v) {
#pragma unroll
    for (int o = 16; o; o >>= 1) v += __shfl_xor_sync(0xFFFFFFFFu, v, o);
    return v;
}

__global__ __launch_bounds__(256)
void softmax_kernel(float* __restrict__ S, int N)
{
    __shared__ float buf[NTOK];      // 32 KB row cache
    __shared__ float red[8];
    __shared__ float bcast;

    const int row = blockIdx.x;
    float* Sr = S + (size_t)row * N;
    const int tid = threadIdx.x;
    const int wid = tid >> 5, lid = tid & 31;

    float m = -1e30f;
    for (int i = tid; i < N; i += 256) {
        float v = Sr[i];
        buf[i] = v;
        m = fmaxf(m, v);
    }
    m = warpMax(m);
    if (lid == 0) red[wid] = m;
    __syncthreads();
    if (wid == 0) {
        float v = (lid < 8) ? red[lid] : -1e30f;
        v = warpMax(v);
        if (lid == 0) bcast = v;
    }
    __syncthreads();
    const float rowmax = bcast;

    float s = 0.f;
    for (int i = tid; i < N; i += 256) {
        float e = __expf(buf[i] - rowmax);
        buf[i] = e;
        s += e;
    }
    s = warpSum(s);
    if (lid == 0) red[wid] = s;
    __syncthreads();
    if (wid == 0) {
        float v = (lid < 8) ? red[lid] : 0.f;
        v = warpSum(v);
        if (lid == 0) bcast = v;
    }
    __syncthreads();
    const float inv = 1.f / bcast;

    for (int i = tid; i < N; i += 256)
        Sr[i] = buf[i] * inv;
}

// ---------------------------------------------------------------------------
// LayerNorm over D=1024 per row. One block (256 thr) per row.
// ---------------------------------------------------------------------------
__global__ __launch_bounds__(256)
void ln_kernel(const float* __restrict__ H, const float* __restrict__ gamma,
               const float* __restrict__ beta, float* __restrict__ out)
{
    __shared__ float buf[DIM];
    __shared__ float red[8];
    __shared__ float bcast;

    const int row = blockIdx.x;
    const float* Hr = H + (size_t)row * DIM;
    const int tid = threadIdx.x;
    const int wid = tid >> 5, lid = tid & 31;

    float s = 0.f;
    for (int i = tid; i < DIM; i += 256) {
        float v = Hr[i];
        buf[i] = v;
        s += v;
    }
    s = warpSum(s);
    if (lid == 0) red[wid] = s;
    __syncthreads();
    if (wid == 0) {
        float v = (lid < 8) ? red[lid] : 0.f;
        v = warpSum(v);
        if (lid == 0) bcast = v;
    }
    __syncthreads();
    const float mu = bcast * (1.f / DIM);

    float vs = 0.f;
    for (int i = tid; i < DIM; i += 256) {
        float d = buf[i] - mu;
        vs += d * d;
    }
    vs = warpSum(vs);
    if (lid == 0) red[wid] = vs;
    __syncthreads();
    if (wid == 0) {
        float v = (lid < 8) ? red[lid] : 0.f;
        v = warpSum(v);
        if (lid == 0) bcast = v;
    }
    __syncthreads();
    const float rstd = rsqrtf(bcast * (1.f / DIM) + 1e-5f);

    float* Or = out + (size_t)row * DIM;
    for (int i = tid; i < DIM; i += 256)
        Or[i] = (buf[i] - mu) * rstd * gamma[i] + beta[i];
}

// ---------------------------------------------------------------------------
// Launch
// ---------------------------------------------------------------------------
extern "C" void kernel_launch(void* const* d_in, const int* in_sizes, int n_in,
                              void* d_out, int out_size)
{
    const float* x     = (const float*)d_in[0];
    const int*   ids   = (const int*)  d_in[1];
    const float* Wq    = (const float*)d_in[2];
    const float* bq    = (const float*)d_in[3];
    const float* Wk    = (const float*)d_in[4];
    const float* bk    = (const float*)d_in[5];
    const float* Wv    = (const float*)d_in[6];
    const float* bv    = (const float*)d_in[7];
    const float* Wo    = (const float*)d_in[8];
    const float* bo    = (const float*)d_in[9];
    const float* gamma = (const float*)d_in[10];
    const float* beta  = (const float*)d_in[11];

    float *Q, *K, *V, *O, *S;
    cudaGetSymbolAddress((void**)&Q, g_Q);
    cudaGetSymbolAddress((void**)&K, g_K);
    cudaGetSymbolAddress((void**)&V, g_V);
    cudaGetSymbolAddress((void**)&O, g_O);
    cudaGetSymbolAddress((void**)&S, g_S);
    float* H = Q;  // g_Q is dead after the score GEMM; reuse for H

    const float scale = 0.088388347648318447f;  // 1/sqrt(128)

    dim3 blk(256);
    dim3 gProj(DIM / BN, NTOK / BM);   // (8, 64)
    dim3 gScore(NTOK / BN, NTOK / BM); // (64, 64)

    gemm_nn_kernel<<<gProj, blk>>>(x, Wq, bq, nullptr, Q, NTOK, DIM, DIM);
    gemm_nn_kernel<<<gProj, blk>>>(x, Wk, bk, nullptr, K, NTOK, DIM, DIM);
    gemm_nn_kernel<<<gProj, blk>>>(x, Wv, bv, nullptr, V, NTOK, DIM, DIM);

    gemm_nt_mask_kernel<<<gScore, blk>>>(Q, K, ids, S, NTOK, DIM, scale);

    softmax_kernel<<<NTOK, blk>>>(S, NTOK);

    gemm_nn_kernel<<<gProj, blk>>>(S, V, nullptr, nullptr, O, NTOK, DIM, NTOK);

    gemm_nn_kernel<<<gProj, blk>>>(O, Wo, bo, x, H, NTOK, DIM, DIM);

    ln_kernel<<<NTOK, blk>>>(H, gamma, beta, (float*)d_out);
}

// round 2
// speedup vs baseline: 4.8416x; 4.8416x over previous
#include <cuda_runtime.h>
#include <cuda_bf16.h>
#include <math.h>
#include <stdint.h>

// ---------------------------------------------------------------------------
// GlobalInteractionModule: cross-community attention, N=8192, D=1024.
// Round 2: all GEMMs on tf32 tensor cores (mma.sync.m16n8k8), fp32 accum.
// ---------------------------------------------------------------------------

#define NTOK 8192
#define DIM  1024

__device__ float g_Q[(size_t)NTOK * DIM];
__device__ float g_K[(size_t)NTOK * DIM];
__device__ float g_V[(size_t)NTOK * DIM];
__device__ float g_O[(size_t)NTOK * DIM];
__device__ float g_S[(size_t)NTOK * NTOK];

#define BM 128
#define BN 128
#define BK 32

// smem strides chosen for conflict-free fragment loads (see analysis):
//   A-style [128][36]: bank = 4*g + tig  (unique over warp)
//   B-style [32][136]: bank = 8*tig + g  (unique over warp)
#define SA 36
#define SB 136

__device__ __forceinline__ uint32_t f2tf32(float x) {
    uint32_t r;
    asm("cvt.rna.tf32.f32 %0, %1;" : "=r"(r) : "f"(x));
    return r;
}

__device__ __forceinline__ void mma_tf32(float c[4], const uint32_t a[4], const uint32_t b[2]) {
    asm volatile(
        "mma.sync.aligned.m16n8k8.row.col.f32.tf32.tf32.f32 "
        "{%0,%1,%2,%3}, {%4,%5,%6,%7}, {%8,%9}, {%0,%1,%2,%3};\n"
        : "+f"(c[0]), "+f"(c[1]), "+f"(c[2]), "+f"(c[3])
        : "r"(a[0]), "r"(a[1]), "r"(a[2]), "r"(a[3]), "r"(b[0]), "r"(b[1]));
}

// ---------------------------------------------------------------------------
// NN GEMM: C[M,N] = A[M,K] @ B[K,N] (+bias[N]) (+resid) — tf32 tensor core.
// 128x128x32 CTA tile, 8 warps in 2x4 grid, 64x32 warp tile (4x4 mma tiles).
// ---------------------------------------------------------------------------
__global__ __launch_bounds__(256)
void gemm_nn_tc(const float* __restrict__ A, const float* __restrict__ B,
                const float* __restrict__ bias, const float* __restrict__ resid,
                float* __restrict__ C, int M, int N, int K)
{
    __shared__ uint32_t As[BM][SA];   // [row][k]
    __shared__ uint32_t Bs[BK][SB];   // [k][col]

    const int bm = blockIdx.y * BM;
    const int bn = blockIdx.x * BN;
    const int tid  = threadIdx.x;
    const int warp = tid >> 5;
    const int lane = tid & 31;
    const int g    = lane >> 2;   // 0..7
    const int tig  = lane & 3;    // 0..3
    const int wm   = (warp >> 2) * 64;   // warp m offset: 0 or 64
    const int wn   = (warp & 3) * 32;    // warp n offset: 0/32/64/96

    float acc[4][4][4];
#pragma unroll
    for (int i = 0; i < 4; i++)
#pragma unroll
        for (int j = 0; j < 4; j++)
#pragma unroll
            for (int r = 0; r < 4; r++) acc[i][j][r] = 0.f;

    for (int k0 = 0; k0 < K; k0 += BK) {
        // A tile: 128x32, 1024 float4s, 4 per thread
#pragma unroll
        for (int i = 0; i < 4; i++) {
            int f = tid + i * 256;
            int r = f >> 3, c4 = (f & 7) << 2;
            float4 v = *(const float4*)&A[(size_t)(bm + r) * K + k0 + c4];
            uint4 t = { f2tf32(v.x), f2tf32(v.y), f2tf32(v.z), f2tf32(v.w) };
            *(uint4*)&As[r][c4] = t;
        }
        // B tile: 32x128
#pragma unroll
        for (int i = 0; i < 4; i++) {
            int f = tid + i * 256;
            int r = f >> 5, c4 = (f & 31) << 2;
            float4 v = *(const float4*)&B[(size_t)(k0 + r) * N + bn + c4];
            uint4 t = { f2tf32(v.x), f2tf32(v.y), f2tf32(v.z), f2tf32(v.w) };
            *(uint4*)&Bs[r][c4] = t;
        }
        __syncthreads();

#pragma unroll
        for (int ks = 0; ks < BK; ks += 8) {
            uint32_t af[4][4];
#pragma unroll
            for (int mt = 0; mt < 4; mt++) {
                int rb = wm + mt * 16;
                af[mt][0] = As[rb + g][ks + tig];
                af[mt][1] = As[rb + g + 8][ks + tig];
                af[mt][2] = As[rb + g][ks + tig + 4];
                af[mt][3] = As[rb + g + 8][ks + tig + 4];
            }
            uint32_t bf[4][2];
#pragma unroll
            for (int nt = 0; nt < 4; nt++) {
                int cb = wn + nt * 8;
                bf[nt][0] = Bs[ks + tig][cb + g];
                bf[nt][1] = Bs[ks + tig + 4][cb + g];
            }
#pragma unroll
            for (int mt = 0; mt < 4; mt++)
#pragma unroll
                for (int nt = 0; nt < 4; nt++)
                    mma_tf32(acc[mt][nt], af[mt], bf[nt]);
        }
        __syncthreads();
    }

    // Epilogue: c0,c1 -> row g, cols 2t,2t+1 ; c2,c3 -> row g+8
#pragma unroll
    for (int mt = 0; mt < 4; mt++) {
#pragma unroll
        for (int nt = 0; nt < 4; nt++) {
            int r0 = bm + wm + mt * 16 + g;
            int c  = bn + wn + nt * 8 + 2 * tig;
#pragma unroll
            for (int half = 0; half < 2; half++) {
                int r = r0 + half * 8;
                float v0 = acc[mt][nt][2 * half];
                float v1 = acc[mt][nt][2 * half + 1];
                if (bias) { v0 += bias[c]; v1 += bias[c + 1]; }
                if (resid) {
                    const float2 rr = *(const float2*)&resid[(size_t)r * N + c];
                    v0 += rr.x; v1 += rr.y;
                }
                float2 out = { v0, v1 };
                *(float2*)&C[(size_t)r * N + c] = out;
            }
        }
    }
}

// ---------------------------------------------------------------------------
// NT GEMM + mask: S = (Q @ K^T)*scale, -1e30 where ids equal.
// B col-major == K-matrix row-major, so K tile uses the A-style smem layout.
// ---------------------------------------------------------------------------
__global__ __launch_bounds__(256)
void gemm_nt_mask_tc(const float* __restrict__ Q, const float* __restrict__ Kmat,
                     const int* __restrict__ ids, float* __restrict__ S,
                     int N, int D, float scale)
{
    __shared__ uint32_t As[BM][SA];   // Q rows [m][k]
    __shared__ uint32_t Ks[BM][SA];   // K rows [n][k]
    __shared__ int idsR[BM];
    __shared__ int idsC[BN];

    const int bm = blockIdx.y * BM;
    const int bn = blockIdx.x * BN;
    const int tid  = threadIdx.x;
    const int warp = tid >> 5;
    const int lane = tid & 31;
    const int g    = lane >> 2;
    const int tig  = lane & 3;
    const int wm   = (warp >> 2) * 64;
    const int wn   = (warp & 3) * 32;

    if (tid < 128)       idsR[tid]       = ids[bm + tid];
    else                 idsC[tid - 128] = ids[bn + tid - 128];

    float acc[4][4][4];
#pragma unroll
    for (int i = 0; i < 4; i++)
#pragma unroll
        for (int j = 0; j < 4; j++)
#pragma unroll
            for (int r = 0; r < 4; r++) acc[i][j][r] = 0.f;

    for (int k0 = 0; k0 < D; k0 += BK) {
#pragma unroll
        for (int i = 0; i < 4; i++) {
            int f = tid + i * 256;
            int r = f >> 3, c4 = (f & 7) << 2;
            float4 v = *(const float4*)&Q[(size_t)(bm + r) * D + k0 + c4];
            uint4 t = { f2tf32(v.x), f2tf32(v.y), f2tf32(v.z), f2tf32(v.w) };
            *(uint4*)&As[r][c4] = t;
        }
#pragma unroll
        for (int i = 0; i < 4; i++) {
            int f = tid + i * 256;
            int r = f >> 3, c4 = (f & 7) << 2;
            float4 v = *(const float4*)&Kmat[(size_t)(bn + r) * D + k0 + c4];
            uint4 t = { f2tf32(v.x), f2tf32(v.y), f2tf32(v.z), f2tf32(v.w) };
            *(uint4*)&Ks[r][c4] = t;
        }
        __syncthreads();

#pragma unroll
        for (int ks = 0; ks < BK; ks += 8) {
            uint32_t af[4][4];
#pragma unroll
            for (int mt = 0; mt < 4; mt++) {
                int rb = wm + mt * 16;
                af[mt][0] = As[rb + g][ks + tig];
                af[mt][1] = As[rb + g + 8][ks + tig];
                af[mt][2] = As[rb + g][ks + tig + 4];
                af[mt][3] = As[rb + g + 8][ks + tig + 4];
            }
            uint32_t bf[4][2];
#pragma unroll
            for (int nt = 0; nt < 4; nt++) {
                int cb = wn + nt * 8;
                bf[nt][0] = Ks[cb + g][ks + tig];
                bf[nt][1] = Ks[cb + g][ks + tig + 4];
            }
#pragma unroll
            for (int mt = 0; mt < 4; mt++)
#pragma unroll
                for (int nt = 0; nt < 4; nt++)
                    mma_tf32(acc[mt][nt], af[mt], bf[nt]);
        }
        __syncthreads();
    }

#pragma unroll
    for (int mt = 0; mt < 4; mt++) {
#pragma unroll
        for (int nt = 0; nt < 4; nt++) {
            int rl0 = wm + mt * 16 + g;
            int cl  = wn + nt * 8 + 2 * tig;
            int idc0 = idsC[cl], idc1 = idsC[cl + 1];
#pragma unroll
            for (int half = 0; half < 2; half++) {
                int rl = rl0 + half * 8;
                int idr = idsR[rl];
                float v0 = (idr == idc0) ? -1e30f : acc[mt][nt][2 * half] * scale;
                float v1 = (idr == idc1) ? -1e30f : acc[mt][nt][2 * half + 1] * scale;
                float2 out = { v0, v1 };
                *(float2*)&S[(size_t)(bm + rl) * N + bn + cl] = out;
            }
        }
    }
}

// ---------------------------------------------------------------------------
// Row softmax over N=8192, in-place.
// ---------------------------------------------------------------------------
__device__ __forceinline__ float warpMax(float v) {
#pragma unroll
    for (int o = 16; o; o >>= 1) v = fmaxf(v, __shfl_xor_sync(0xFFFFFFFFu, v, o));
    return v;
}
__device__ __forceinline__ float warpSum(float v) {
#pragma unroll
    for (int o = 16; o; o >>= 1) v += __shfl_xor_sync(0xFFFFFFFFu, v, o);
    return v;
}

__global__ __launch_bounds__(256)
void softmax_kernel(float* __restrict__ S, int N)
{
    __shared__ float buf[NTOK];
    __shared__ float red[8];
    __shared__ float bcast;

    const int row = blockIdx.x;
    float* Sr = S + (size_t)row * N;
    const int tid = threadIdx.x;
    const int wid = tid >> 5, lid = tid & 31;

    float m = -1e30f;
    for (int i = tid; i < N; i += 256) {
        float v = Sr[i];
        buf[i] = v;
        m = fmaxf(m, v);
    }
    m = warpMax(m);
    if (lid == 0) red[wid] = m;
    __syncthreads();
    if (wid == 0) {
        float v = (lid < 8) ? red[lid] : -1e30f;
        v = warpMax(v);
        if (lid == 0) bcast = v;
    }
    __syncthreads();
    const float rowmax = bcast;

    float s = 0.f;
    for (int i = tid; i < N; i += 256) {
        float e = __expf(buf[i] - rowmax);
        buf[i] = e;
        s += e;
    }
    s = warpSum(s);
    if (lid == 0) red[wid] = s;
    __syncthreads();
    if (wid == 0) {
        float v = (lid < 8) ? red[lid] : 0.f;
        v = warpSum(v);
        if (lid == 0) bcast = v;
    }
    __syncthreads();
    const float inv = 1.f / bcast;

    for (int i = tid; i < N; i += 256)
        Sr[i] = buf[i] * inv;
}

// ---------------------------------------------------------------------------
// LayerNorm over D=1024 per row.
// ---------------------------------------------------------------------------
__global__ __launch_bounds__(256)
void ln_kernel(const float* __restrict__ H, const float* __restrict__ gamma,
               const float* __restrict__ beta, float* __restrict__ out)
{
    __shared__ float buf[DIM];
    __shared__ float red[8];
    __shared__ float bcast;

    const int row = blockIdx.x;
    const float* Hr = H + (size_t)row * DIM;
    const int tid = threadIdx.x;
    const int wid = tid >> 5, lid = tid & 31;

    float s = 0.f;
    for (int i = tid; i < DIM; i += 256) {
        float v = Hr[i];
        buf[i] = v;
        s += v;
    }
    s = warpSum(s);
    if (lid == 0) red[wid] = s;
    __syncthreads();
    if (wid == 0) {
        float v = (lid < 8) ? red[lid] : 0.f;
        v = warpSum(v);
        if (lid == 0) bcast = v;
    }
    __syncthreads();
    const float mu = bcast * (1.f / DIM);

    float vs = 0.f;
    for (int i = tid; i < DIM; i += 256) {
        float d = buf[i] - mu;
        vs += d * d;
    }
    vs = warpSum(vs);
    if (lid == 0) red[wid] = vs;
    __syncthreads();
    if (wid == 0) {
        float v = (lid < 8) ? red[lid] : 0.f;
        v = warpSum(v);
        if (lid == 0) bcast = v;
    }
    __syncthreads();
    const float rstd = rsqrtf(bcast * (1.f / DIM) + 1e-5f);

    float* Or = out + (size_t)row * DIM;
    for (int i = tid; i < DIM; i += 256)
        Or[i] = (buf[i] - mu) * rstd * gamma[i] + beta[i];
}

// ---------------------------------------------------------------------------
// Launch
// ---------------------------------------------------------------------------
extern "C" void kernel_launch(void* const* d_in, const int* in_sizes, int n_in,
                              void* d_out, int out_size)
{
    const float* x     = (const float*)d_in[0];
    const int*   ids   = (const int*)  d_in[1];
    const float* Wq    = (const float*)d_in[2];
    const float* bq    = (const float*)d_in[3];
    const float* Wk    = (const float*)d_in[4];
    const float* bk    = (const float*)d_in[5];
    const float* Wv    = (const float*)d_in[6];
    const float* bv    = (const float*)d_in[7];
    const float* Wo    = (const float*)d_in[8];
    const float* bo    = (const float*)d_in[9];
    const float* gamma = (const float*)d_in[10];
    const float* beta  = (const float*)d_in[11];

    float *Q, *K, *V, *O, *S;
    cudaGetSymbolAddress((void**)&Q, g_Q);
    cudaGetSymbolAddress((void**)&K, g_K);
    cudaGetSymbolAddress((void**)&V, g_V);
    cudaGetSymbolAddress((void**)&O, g_O);
    cudaGetSymbolAddress((void**)&S, g_S);
    float* H = Q;  // g_Q dead after score GEMM; reuse as H

    const float scale = 0.088388347648318447f;  // 1/sqrt(128)

    dim3 blk(256);
    dim3 gProj(DIM / BN, NTOK / BM);   // (8, 64)
    dim3 gScore(NTOK / BN, NTOK / BM); // (64, 64)

    gemm_nn_tc<<<gProj, blk>>>(x, Wq, bq, nullptr, Q, NTOK, DIM, DIM);
    gemm_nn_tc<<<gProj, blk>>>(x, Wk, bk, nullptr, K, NTOK, DIM, DIM);
    gemm_nn_tc<<<gProj, blk>>>(x, Wv, bv, nullptr, V, NTOK, DIM, DIM);

    gemm_nt_mask_tc<<<gScore, blk>>>(Q, K, ids, S, NTOK, DIM, scale);

    softmax_kernel<<<NTOK, blk>>>(S, NTOK);

    gemm_nn_tc<<<gProj, blk>>>(S, V, nullptr, nullptr, O, NTOK, DIM, NTOK);

    gemm_nn_tc<<<gProj, blk>>>(O, Wo, bo, x, H, NTOK, DIM, DIM);

    ln_kernel<<<NTOK, blk>>>(H, gamma, beta, (float*)d_out);
}

// round 4
// speedup vs baseline: 8.6094x; 1.7782x over previous
#include <cuda_runtime.h>
#include <cuda_bf16.h>
#include <math.h>
#include <stdint.h>

// ---------------------------------------------------------------------------
// GlobalInteractionModule: cross-community attention, N=8192, D=1024.
// Round 4: bf16 mma.sync.m16n8k16, cp.async double-buffered.
// Fix vs R3: NN B-tile smem stride SB 72 -> 136 (R3 overran the array).
// ---------------------------------------------------------------------------

#define NTOK 8192
#define DIM  1024

#define BM 128
#define BN 128
#define BK 32        // k-extent per mainloop iter (bf16 elements)
#define KP 16        // packed uint32 (bf16x2) words per A-tile row
#define SA 20        // A-style smem row stride (words): bank=20g+tig, conflict-free
#define SB 136       // B-style smem row stride (words): 136%32=8 -> bank=8*tig+g, conflict-free

// --------------------------- scratch (static) ------------------------------
__device__ __nv_bfloat16 g_xb[(size_t)NTOK * DIM];
__device__ uint32_t      g_Wqp[(size_t)(DIM / 2) * DIM];
__device__ uint32_t      g_Wkp[(size_t)(DIM / 2) * DIM];
__device__ uint32_t      g_Wvp[(size_t)(DIM / 2) * DIM];
__device__ uint32_t      g_Wop[(size_t)(DIM / 2) * DIM];
__device__ __nv_bfloat16 g_Qb[(size_t)NTOK * DIM];
__device__ __nv_bfloat16 g_Kb[(size_t)NTOK * DIM];
__device__ __nv_bfloat16 g_Vt[(size_t)DIM * NTOK];     // V transposed [feat][tok]
__device__ __nv_bfloat16 g_Ob[(size_t)NTOK * DIM];
__device__ float         g_S [(size_t)NTOK * NTOK];    // fp32 scores (256 MB)
__device__ __nv_bfloat16 g_P [(size_t)NTOK * NTOK];    // bf16 probs (128 MB)
__device__ float         g_H [(size_t)NTOK * DIM];

// ------------------------------ helpers ------------------------------------
__device__ __forceinline__ void cp16(void* smem, const void* gmem) {
    uint32_t sa = (uint32_t)__cvta_generic_to_shared(smem);
    asm volatile("cp.async.cg.shared.global [%0], [%1], 16;\n" :: "r"(sa), "l"(gmem));
}
#define CP_COMMIT() asm volatile("cp.async.commit_group;\n")
#define CP_WAIT0()  asm volatile("cp.async.wait_group 0;\n")

__device__ __forceinline__ void mma_bf16(float c[4], const uint32_t a[4], const uint32_t b[2]) {
    asm volatile(
        "mma.sync.aligned.m16n8k16.row.col.f32.bf16.bf16.f32 "
        "{%0,%1,%2,%3}, {%4,%5,%6,%7}, {%8,%9}, {%0,%1,%2,%3};\n"
        : "+f"(c[0]), "+f"(c[1]), "+f"(c[2]), "+f"(c[3])
        : "r"(a[0]), "r"(a[1]), "r"(a[2]), "r"(a[3]), "r"(b[0]), "r"(b[1]));
}

// ------------------------- convert / pack kernels --------------------------
__global__ __launch_bounds__(256)
void f2b_kernel(const float* __restrict__ in, __nv_bfloat16* __restrict__ out, int n)
{
    int i = (blockIdx.x * 256 + threadIdx.x) * 4;
    if (i < n) {
        float4 v = *(const float4*)&in[i];
        *(__nv_bfloat162*)&out[i]     = __floats2bfloat162_rn(v.x, v.y);
        *(__nv_bfloat162*)&out[i + 2] = __floats2bfloat162_rn(v.z, v.w);
    }
}

// Pack W[K,N] fp32 -> Wp[K/2,N] uint32: word = bf16(W[2k2][n]) | bf16(W[2k2+1][n])<<16
__global__ __launch_bounds__(256)
void packw_kernel(const float* __restrict__ W, uint32_t* __restrict__ Wp, int K, int N)
{
    int idx = blockIdx.x * 256 + threadIdx.x;
    int total = (K / 2) * N;
    if (idx < total) {
        int k2 = idx / N, n = idx - k2 * N;
        float a = W[(size_t)(2 * k2) * N + n];
        float b = W[(size_t)(2 * k2 + 1) * N + n];
        __nv_bfloat162 p = __floats2bfloat162_rn(a, b);
        Wp[idx] = *(uint32_t*)&p;
    }
}

// ---------------------------------------------------------------------------
// NN GEMM (bf16 TC): C[M,N] = A[M,K] @ B[K,N] (+bias) (+resid)
//   MODE 0: out bf16 row-major, +bias          (Q, K)
//   MODE 1: out bf16 TRANSPOSED [N][M], +bias  (V -> Vt)
//   MODE 2: out fp32 row-major, +bias +resid   (final H)
// ---------------------------------------------------------------------------
template<int MODE>
__global__ __launch_bounds__(256)
void gemm_nn_bf16(const __nv_bfloat16* __restrict__ A, const uint32_t* __restrict__ Bp,
                  const float* __restrict__ bias, const float* __restrict__ resid,
                  void* __restrict__ Cout, int M, int N, int K)
{
    __shared__ uint32_t As[2][BM][SA];
    __shared__ uint32_t Bs[2][KP][SB];

    const int bm = blockIdx.y * BM;
    const int bn = blockIdx.x * BN;
    const int tid  = threadIdx.x;
    const int warp = tid >> 5;
    const int lane = tid & 31;
    const int g    = lane >> 2;
    const int tig  = lane & 3;
    const int wm   = (warp >> 2) * 64;
    const int wn   = (warp & 3) * 32;

    float acc[4][4][4];
#pragma unroll
    for (int i = 0; i < 4; i++)
#pragma unroll
        for (int j = 0; j < 4; j++)
#pragma unroll
            for (int r = 0; r < 4; r++) acc[i][j][r] = 0.f;

    const int NIT = K / BK;

    auto stage = [&](int s, int k0) {
        // A tile: 128 rows x 64B -> 512 x 16B chunks (word offsets 0,4,8,12)
#pragma unroll
        for (int i = 0; i < 2; i++) {
            int id = tid + i * 256;
            int row = id >> 2, ch = id & 3;
            cp16(&As[s][row][ch * 4], &A[(size_t)(bm + row) * K + k0 + ch * 8]);
        }
        // B tile: 16 packed rows x 128 words -> 512 x 16B chunks
        int k2 = k0 >> 1;
#pragma unroll
        for (int i = 0; i < 2; i++) {
            int id = tid + i * 256;
            int r = id >> 5, ch = id & 31;
            cp16(&Bs[s][r][ch * 4], &Bp[(size_t)(k2 + r) * N + bn + ch * 4]);
        }
    };

    stage(0, 0);
    CP_COMMIT();

    for (int it = 0; it < NIT; it++) {
        CP_WAIT0();
        __syncthreads();
        if (it + 1 < NIT) { stage((it + 1) & 1, (it + 1) * BK); CP_COMMIT(); }
        const int s = it & 1;

#pragma unroll
        for (int ko = 0; ko < KP; ko += 8) {   // 2 k-steps of 16
            uint32_t af[4][4];
#pragma unroll
            for (int mt = 0; mt < 4; mt++) {
                int rb = wm + mt * 16;
                af[mt][0] = As[s][rb + g][ko + tig];
                af[mt][1] = As[s][rb + g + 8][ko + tig];
                af[mt][2] = As[s][rb + g][ko + tig + 4];
                af[mt][3] = As[s][rb + g + 8][ko + tig + 4];
            }
            uint32_t bf[4][2];
#pragma unroll
            for (int nt = 0; nt < 4; nt++) {
                int cb = wn + nt * 8;
                bf[nt][0] = Bs[s][ko + tig][cb + g];
                bf[nt][1] = Bs[s][ko + tig + 4][cb + g];
            }
#pragma unroll
            for (int mt = 0; mt < 4; mt++)
#pragma unroll
                for (int nt = 0; nt < 4; nt++)
                    mma_bf16(acc[mt][nt], af[mt], bf[nt]);
        }
        __syncthreads();
    }

    // epilogue
#pragma unroll
    for (int mt = 0; mt < 4; mt++) {
#pragma unroll
        for (int nt = 0; nt < 4; nt++) {
            int r0 = bm + wm + mt * 16 + g;
            int c  = bn + wn + nt * 8 + 2 * tig;
#pragma unroll
            for (int half = 0; half < 2; half++) {
                int r = r0 + half * 8;
                float v0 = acc[mt][nt][2 * half];
                float v1 = acc[mt][nt][2 * half + 1];
                if (bias) { v0 += bias[c]; v1 += bias[c + 1]; }
                if (MODE == 0) {
                    __nv_bfloat162 p = __floats2bfloat162_rn(v0, v1);
                    *(__nv_bfloat162*)((__nv_bfloat16*)Cout + (size_t)r * N + c) = p;
                } else if (MODE == 1) {
                    __nv_bfloat16* Ct = (__nv_bfloat16*)Cout;
                    Ct[(size_t)c * M + r]       = __float2bfloat16_rn(v0);
                    Ct[(size_t)(c + 1) * M + r] = __float2bfloat16_rn(v1);
                } else {
                    float* Cf = (float*)Cout;
                    const float2 rr = *(const float2*)&resid[(size_t)r * N + c];
                    float2 out = { v0 + rr.x, v1 + rr.y };
                    *(float2*)&Cf[(size_t)r * N + c] = out;
                }
            }
        }
    }
}

// ---------------------------------------------------------------------------
// NT GEMM (bf16 TC): C[M,N] = A[M,K] @ Bmat[N,K]^T
//   MODE 0: scores -> fp32, *scale, mask -1e30 where ids equal
//   MODE 1: PV     -> bf16 row-major, plain
// ---------------------------------------------------------------------------
template<int MODE>
__global__ __launch_bounds__(256)
void gemm_nt_bf16(const __nv_bfloat16* __restrict__ A, const __nv_bfloat16* __restrict__ Bmat,
                  const int* __restrict__ ids, void* __restrict__ Cout,
                  int M, int N, int K, float scale)
{
    __shared__ uint32_t As[2][BM][SA];
    __shared__ uint32_t Ks[2][BN][SA];
    __shared__ int idsR[BM];
    __shared__ int idsC[BN];

    const int bm = blockIdx.y * BM;
    const int bn = blockIdx.x * BN;
    const int tid  = threadIdx.x;
    const int warp = tid >> 5;
    const int lane = tid & 31;
    const int g    = lane >> 2;
    const int tig  = lane & 3;
    const int wm   = (warp >> 2) * 64;
    const int wn   = (warp & 3) * 32;

    if (MODE == 0) {
        if (tid < 128)       idsR[tid]       = ids[bm + tid];
        else                 idsC[tid - 128] = ids[bn + tid - 128];
    }

    float acc[4][4][4];
#pragma unroll
    for (int i = 0; i < 4; i++)
#pragma unroll
        for (int j = 0; j < 4; j++)
#pragma unroll
            for (int r = 0; r < 4; r++) acc[i][j][r] = 0.f;

    const int NIT = K / BK;

    auto stage = [&](int s, int k0) {
#pragma unroll
        for (int i = 0; i < 2; i++) {
            int id = tid + i * 256;
            int row = id >> 2, ch = id & 3;
            cp16(&As[s][row][ch * 4], &A[(size_t)(bm + row) * K + k0 + ch * 8]);
        }
#pragma unroll
        for (int i = 0; i < 2; i++) {
            int id = tid + i * 256;
            int row = id >> 2, ch = id & 3;
            cp16(&Ks[s][row][ch * 4], &Bmat[(size_t)(bn + row) * K + k0 + ch * 8]);
        }
    };

    stage(0, 0);
    CP_COMMIT();

    for (int it = 0; it < NIT; it++) {
        CP_WAIT0();
        __syncthreads();
        if (it + 1 < NIT) { stage((it + 1) & 1, (it + 1) * BK); CP_COMMIT(); }
        const int s = it & 1;

#pragma unroll
        for (int ko = 0; ko < KP; ko += 8) {
            uint32_t af[4][4];
#pragma unroll
            for (int mt = 0; mt < 4; mt++) {
                int rb = wm + mt * 16;
                af[mt][0] = As[s][rb + g][ko + tig];
                af[mt][1] = As[s][rb + g + 8][ko + tig];
                af[mt][2] = As[s][rb + g][ko + tig + 4];
                af[mt][3] = As[s][rb + g + 8][ko + tig + 4];
            }
            uint32_t bf[4][2];
#pragma unroll
            for (int nt = 0; nt < 4; nt++) {
                int cb = wn + nt * 8;
                bf[nt][0] = Ks[s][cb + g][ko + tig];
                bf[nt][1] = Ks[s][cb + g][ko + tig + 4];
            }
#pragma unroll
            for (int mt = 0; mt < 4; mt++)
#pragma unroll
                for (int nt = 0; nt < 4; nt++)
                    mma_bf16(acc[mt][nt], af[mt], bf[nt]);
        }
        __syncthreads();
    }

#pragma unroll
    for (int mt = 0; mt < 4; mt++) {
#pragma unroll
        for (int nt = 0; nt < 4; nt++) {
            int rl0 = wm + mt * 16 + g;
            int cl  = wn + nt * 8 + 2 * tig;
#pragma unroll
            for (int half = 0; half < 2; half++) {
                int rl = rl0 + half * 8;
                float v0 = acc[mt][nt][2 * half];
                float v1 = acc[mt][nt][2 * half + 1];
                if (MODE == 0) {
                    int idr = idsR[rl];
                    v0 = (idr == idsC[cl])     ? -1e30f : v0 * scale;
                    v1 = (idr == idsC[cl + 1]) ? -1e30f : v1 * scale;
                    float2 out = { v0, v1 };
                    *(float2*)((float*)Cout + (size_t)(bm + rl) * N + bn + cl) = out;
                } else {
                    __nv_bfloat162 p = __floats2bfloat162_rn(v0, v1);
                    *(__nv_bfloat162*)((__nv_bfloat16*)Cout + (size_t)(bm + rl) * N + bn + cl) = p;
                }
            }
        }
    }
}

// ---------------------------------------------------------------------------
// Row softmax: S fp32 -> P bf16.
// ---------------------------------------------------------------------------
__device__ __forceinline__ float warpMax(float v) {
#pragma unroll
    for (int o = 16; o; o >>= 1) v = fmaxf(v, __shfl_xor_sync(0xFFFFFFFFu, v, o));
    return v;
}
__device__ __forceinline__ float warpSum(float v) {
#pragma unroll
    for (int o = 16; o; o >>= 1) v += __shfl_xor_sync(0xFFFFFFFFu, v, o);
    return v;
}

__global__ __launch_bounds__(256)
void softmax_kernel(const float* __restrict__ S, __nv_bfloat16* __restrict__ P, int N)
{
    __shared__ float buf[NTOK];
    __shared__ float red[8];
    __shared__ float bcast;

    const int row = blockIdx.x;
    const float* Sr = S + (size_t)row * N;
    const int tid = threadIdx.x;
    const int wid = tid >> 5, lid = tid & 31;

    float m = -1e30f;
    for (int i = tid; i < N; i += 256) {
        float v = Sr[i];
        buf[i] = v;
        m = fmaxf(m, v);
    }
    m = warpMax(m);
    if (lid == 0) red[wid] = m;
    __syncthreads();
    if (wid == 0) {
        float v = (lid < 8) ? red[lid] : -1e30f;
        v = warpMax(v);
        if (lid == 0) bcast = v;
    }
    __syncthreads();
    const float rowmax = bcast;

    float s = 0.f;
    for (int i = tid; i < N; i += 256) {
        float e = __expf(buf[i] - rowmax);
        buf[i] = e;
        s += e;
    }
    s = warpSum(s);
    if (lid == 0) red[wid] = s;
    __syncthreads();
    if (wid == 0) {
        float v = (lid < 8) ? red[lid] : 0.f;
        v = warpSum(v);
        if (lid == 0) bcast = v;
    }
    __syncthreads();
    const float inv = 1.f / bcast;

    __nv_bfloat16* Pr = P + (size_t)row * N;
    for (int i = tid * 2; i < N; i += 512) {
        __nv_bfloat162 p = __floats2bfloat162_rn(buf[i] * inv, buf[i + 1] * inv);
        *(__nv_bfloat162*)&Pr[i] = p;
    }
}

// ---------------------------------------------------------------------------
// LayerNorm over D=1024 per row.
// ---------------------------------------------------------------------------
__global__ __launch_bounds__(256)
void ln_kernel(const float* __restrict__ H, const float* __restrict__ gamma,
               const float* __restrict__ beta, float* __restrict__ out)
{
    __shared__ float buf[DIM];
    __shared__ float red[8];
    __shared__ float bcast;

    const int row = blockIdx.x;
    const float* Hr = H + (size_t)row * DIM;
    const int tid = threadIdx.x;
    const int wid = tid >> 5, lid = tid & 31;

    float s = 0.f;
    for (int i = tid; i < DIM; i += 256) {
        float v = Hr[i];
        buf[i] = v;
        s += v;
    }
    s = warpSum(s);
    if (lid == 0) red[wid] = s;
    __syncthreads();
    if (wid == 0) {
        float v = (lid < 8) ? red[lid] : 0.f;
        v = warpSum(v);
        if (lid == 0) bcast = v;
    }
    __syncthreads();
    const float mu = bcast * (1.f / DIM);

    float vs = 0.f;
    for (int i = tid; i < DIM; i += 256) {
        float d = buf[i] - mu;
        vs += d * d;
    }
    vs = warpSum(vs);
    if (lid == 0) red[wid] = vs;
    __syncthreads();
    if (wid == 0) {
        float v = (lid < 8) ? red[lid] : 0.f;
        v = warpSum(v);
        if (lid == 0) bcast = v;
    }
    __syncthreads();
    const float rstd = rsqrtf(bcast * (1.f / DIM) + 1e-5f);

    float* Or = out + (size_t)row * DIM;
    for (int i = tid; i < DIM; i += 256)
        Or[i] = (buf[i] - mu) * rstd * gamma[i] + beta[i];
}

// ---------------------------------------------------------------------------
// Launch
// ---------------------------------------------------------------------------
extern "C" void kernel_launch(void* const* d_in, const int* in_sizes, int n_in,
                              void* d_out, int out_size)
{
    const float* x     = (const float*)d_in[0];
    const int*   ids   = (const int*)  d_in[1];
    const float* Wq    = (const float*)d_in[2];
    const float* bq    = (const float*)d_in[3];
    const float* Wk    = (const float*)d_in[4];
    const float* bk    = (const float*)d_in[5];
    const float* Wv    = (const float*)d_in[6];
    const float* bv    = (const float*)d_in[7];
    const float* Wo    = (const float*)d_in[8];
    const float* bo    = (const float*)d_in[9];
    const float* gamma = (const float*)d_in[10];
    const float* beta  = (const float*)d_in[11];

    __nv_bfloat16 *xb, *Qb, *Kb, *Vt, *Ob, *P;
    uint32_t *Wqp, *Wkp, *Wvp, *Wop;
    float *S, *H;
    cudaGetSymbolAddress((void**)&xb,  g_xb);
    cudaGetSymbolAddress((void**)&Wqp, g_Wqp);
    cudaGetSymbolAddress((void**)&Wkp, g_Wkp);
    cudaGetSymbolAddress((void**)&Wvp, g_Wvp);
    cudaGetSymbolAddress((void**)&Wop, g_Wop);
    cudaGetSymbolAddress((void**)&Qb,  g_Qb);
    cudaGetSymbolAddress((void**)&Kb,  g_Kb);
    cudaGetSymbolAddress((void**)&Vt,  g_Vt);
    cudaGetSymbolAddress((void**)&Ob,  g_Ob);
    cudaGetSymbolAddress((void**)&S,   g_S);
    cudaGetSymbolAddress((void**)&P,   g_P);
    cudaGetSymbolAddress((void**)&H,   g_H);

    const float scale = 0.088388347648318447f;  // 1/sqrt(128)

    dim3 blk(256);
    dim3 gProj(DIM / BN, NTOK / BM);    // (8, 64)
    dim3 gScore(NTOK / BN, NTOK / BM);  // (64, 64)

    // converts
    f2b_kernel<<<(NTOK * DIM) / (256 * 4), blk>>>(x, xb, NTOK * DIM);
    {
        int pw = (DIM / 2) * DIM;
        int gb = (pw + 255) / 256;
        packw_kernel<<<gb, blk>>>(Wq, Wqp, DIM, DIM);
        packw_kernel<<<gb, blk>>>(Wk, Wkp, DIM, DIM);
        packw_kernel<<<gb, blk>>>(Wv, Wvp, DIM, DIM);
        packw_kernel<<<gb, blk>>>(Wo, Wop, DIM, DIM);
    }

    // QKV
    gemm_nn_bf16<0><<<gProj, blk>>>(xb, Wqp, bq, nullptr, Qb, NTOK, DIM, DIM);
    gemm_nn_bf16<0><<<gProj, blk>>>(xb, Wkp, bk, nullptr, Kb, NTOK, DIM, DIM);
    gemm_nn_bf16<1><<<gProj, blk>>>(xb, Wvp, bv, nullptr, Vt, NTOK, DIM, DIM);

    // scores + mask
    gemm_nt_bf16<0><<<gScore, blk>>>(Qb, Kb, ids, S, NTOK, NTOK, DIM, scale);

    // softmax -> bf16 P
    softmax_kernel<<<NTOK, blk>>>(S, P, NTOK);

    // O = P @ V   (NT against transposed V)
    gemm_nt_bf16<1><<<gProj, blk>>>(P, Vt, nullptr, Ob, NTOK, DIM, NTOK, 1.f);

    // H = O @ Wo + bo + x
    gemm_nn_bf16<2><<<gProj, blk>>>(Ob, Wop, bo, x, H, NTOK, DIM, DIM);

    ln_kernel<<<NTOK, blk>>>(H, gamma, beta, (float*)d_out);
}

// round 7
// speedup vs baseline: 10.1471x; 1.1786x over previous
#include <cuda_runtime.h>
#include <cuda_bf16.h>
#include <stdint.h>
#include <math.h>

// ---------------------------------------------------------------------------
// GlobalInteractionModule: N=8192, D=1024 cross-community attention.
// Round 7 (= R6 resubmit, static-guard removed): unified NT bf16 mma.sync
// GEMM with ldmatrix fragment loads, BK=64 cp.async double buffering.
// ---------------------------------------------------------------------------

#define NTOK 8192
#define DIM  1024

#define BM 128
#define BN 128
#define BK 64          // bf16 elements per mainloop iter
#define SA 36          // smem row stride in words; ldmatrix conflict-free
#define TILE_BYTES (128 * SA * 4)          // 18432
#define STAGE_BYTES (2 * TILE_BYTES)
#define OFF_IDSR 0
#define OFF_IDSC 512
#define OFF_BIAS 1024
#define OFF_T    2048
#define SMEM_TOTAL (OFF_T + 2 * STAGE_BYTES)   // 75776

// --------------------------- scratch (static) ------------------------------
__device__ __nv_bfloat16 g_xb [(size_t)NTOK * DIM];
__device__ __nv_bfloat16 g_Wqt[(size_t)DIM * DIM];   // W^T [out][in] bf16
__device__ __nv_bfloat16 g_Wkt[(size_t)DIM * DIM];
__device__ __nv_bfloat16 g_Wvt[(size_t)DIM * DIM];
__device__ __nv_bfloat16 g_Wot[(size_t)DIM * DIM];
__device__ __nv_bfloat16 g_Qb [(size_t)NTOK * DIM];
__device__ __nv_bfloat16 g_Kb [(size_t)NTOK * DIM];
__device__ __nv_bfloat16 g_Vt [(size_t)DIM * NTOK];  // V transposed [feat][tok]
__device__ __nv_bfloat16 g_Ob [(size_t)NTOK * DIM];
__device__ float         g_S  [(size_t)NTOK * NTOK];
__device__ __nv_bfloat16 g_P  [(size_t)NTOK * NTOK];
__device__ float         g_H  [(size_t)NTOK * DIM];

// ------------------------------ helpers ------------------------------------
__device__ __forceinline__ uint32_t smem_u32(const void* p) {
    uint32_t a;
    asm("{ .reg .u64 t; cvta.to.shared.u64 t, %1; cvt.u32.u64 %0, t; }" : "=r"(a) : "l"(p));
    return a;
}
__device__ __forceinline__ void cp16s(uint32_t saddr, const void* g) {
    asm volatile("cp.async.cg.shared.global [%0], [%1], 16;\n" :: "r"(saddr), "l"(g));
}
#define CP_COMMIT() asm volatile("cp.async.commit_group;\n" ::: "memory")
#define CP_WAIT0()  asm volatile("cp.async.wait_group 0;\n" ::: "memory")

__device__ __forceinline__ void ldsm_x4(uint32_t& r0, uint32_t& r1, uint32_t& r2, uint32_t& r3,
                                        uint32_t addr) {
    asm volatile("ldmatrix.sync.aligned.m8n8.x4.shared.b16 {%0,%1,%2,%3}, [%4];"
                 : "=r"(r0), "=r"(r1), "=r"(r2), "=r"(r3) : "r"(addr));
}
__device__ __forceinline__ void mma_bf16(float c[4], const uint32_t a[4], const uint32_t b[2]) {
    asm volatile(
        "mma.sync.aligned.m16n8k16.row.col.f32.bf16.bf16.f32 "
        "{%0,%1,%2,%3}, {%4,%5,%6,%7}, {%8,%9}, {%0,%1,%2,%3};\n"
        : "+f"(c[0]), "+f"(c[1]), "+f"(c[2]), "+f"(c[3])
        : "r"(a[0]), "r"(a[1]), "r"(a[2]), "r"(a[3]), "r"(b[0]), "r"(b[1]));
}

// ---------------------------------------------------------------------------
// Unified NT GEMM: C[m][n] = sum_k A[m][k] * B[n][k]   (A:[M,K], B:[N,K] bf16)
// MODE 0: scores -> fp32, *scale, mask -1e30 where ids equal
// MODE 1: PV     -> bf16 row-major
// MODE 2: Q/K    -> bf16 row-major, +bias
// MODE 3: V      -> bf16 TRANSPOSED [N][M], +bias
// MODE 4: final  -> fp32 row-major, +bias +resid
// ---------------------------------------------------------------------------
template<int MODE>
__global__ __launch_bounds__(256)
void gemm_nt(const __nv_bfloat16* __restrict__ A, const __nv_bfloat16* __restrict__ B,
             const float* __restrict__ bias, const int* __restrict__ ids,
             const float* __restrict__ resid, void* __restrict__ Cout,
             int M, int N, int K, float scale)
{
    extern __shared__ char smp[];
    const uint32_t base = smem_u32(smp);

    const int tid  = threadIdx.x;
    const int warp = tid >> 5;
    const int lane = tid & 31;
    const int g    = lane >> 2;
    const int tig  = lane & 3;
    const int wm   = (warp >> 2) * 64;
    const int wn   = (warp & 3) * 32;
    const int bm   = blockIdx.y * BM;
    const int bn   = blockIdx.x * BN;

    if (MODE == 0) {
        if (tid < 128)       ((int*)(smp + OFF_IDSR))[tid]       = ids[bm + tid];
        else                 ((int*)(smp + OFF_IDSC))[tid - 128] = ids[bn + tid - 128];
    }
    if (MODE == 2 || MODE == 3 || MODE == 4) {
        if (tid < 128) ((float*)(smp + OFF_BIAS))[tid] = bias[bn + tid];
    }

    float acc[4][4][4];
#pragma unroll
    for (int i = 0; i < 4; i++)
#pragma unroll
        for (int j = 0; j < 4; j++)
#pragma unroll
            for (int r = 0; r < 4; r++) acc[i][j][r] = 0.f;

    const int NIT = K / BK;

    // stage one K-slab: two 128x64 bf16 tiles (A rows bm.., B rows bn..)
    auto stage = [&](int slab) {
        const uint32_t sb = base + OFF_T + (slab & 1) * STAGE_BYTES;
        const int k0 = slab * BK;
#pragma unroll
        for (int i = 0; i < 4; i++) {
            int id = tid + i * 256;            // 0..1023
            int row = id >> 3, ch = id & 7;    // 8 chunks of 16B per row
            cp16s(sb + (row * SA + ch * 4) * 4, &A[(size_t)(bm + row) * K + k0 + ch * 8]);
        }
#pragma unroll
        for (int i = 0; i < 4; i++) {
            int id = tid + i * 256;
            int row = id >> 3, ch = id & 7;
            cp16s(sb + TILE_BYTES + (row * SA + ch * 4) * 4,
                  &B[(size_t)(bn + row) * K + k0 + ch * 8]);
        }
    };

    // per-lane ldmatrix address components
    const int a_row  = (lane & 15);            // + wm + mt*16
    const int a_koff = (lane >> 4) << 2;       // 0 or 4 words (= 8 bf16)
    const int b_row  = (lane & 7) + ((lane >> 4) << 3);  // 0-7 / 8-15
    const int b_koff = ((lane >> 3) & 1) << 2;

    stage(0); CP_COMMIT();

    for (int it = 0; it < NIT; it++) {
        CP_WAIT0();
        __syncthreads();
        if (it + 1 < NIT) { stage(it + 1); CP_COMMIT(); }

        const uint32_t sb = base + OFF_T + (it & 1) * STAGE_BYTES;
        const uint32_t sA = sb;
        const uint32_t sB = sb + TILE_BYTES;

#pragma unroll
        for (int ko = 0; ko < 32; ko += 8) {   // 4 k-steps of 16 bf16
            uint32_t af[4][4];
#pragma unroll
            for (int mt = 0; mt < 4; mt++) {
                uint32_t addr = sA + (((wm + mt * 16 + a_row) * SA) + ko + a_koff) * 4;
                ldsm_x4(af[mt][0], af[mt][1], af[mt][2], af[mt][3], addr);
            }
            uint32_t bf[4][2];
#pragma unroll
            for (int p = 0; p < 2; p++) {      // each x4 covers two n-subtiles
                uint32_t addr = sB + (((wn + p * 16 + b_row) * SA) + ko + b_koff) * 4;
                ldsm_x4(bf[2 * p][0], bf[2 * p][1], bf[2 * p + 1][0], bf[2 * p + 1][1], addr);
            }
#pragma unroll
            for (int mt = 0; mt < 4; mt++)
#pragma unroll
                for (int nt = 0; nt < 4; nt++)
                    mma_bf16(acc[mt][nt], af[mt], bf[nt]);
        }
        __syncthreads();
    }

    // ------------------------------ epilogue -------------------------------
    const int*   idsR_s = (const int*)(smp + OFF_IDSR);
    const int*   idsC_s = (const int*)(smp + OFF_IDSC);
    const float* bias_s = (const float*)(smp + OFF_BIAS);

#pragma unroll
    for (int mt = 0; mt < 4; mt++) {
#pragma unroll
        for (int nt = 0; nt < 4; nt++) {
            int rl0 = wm + mt * 16 + g;
            int cl  = wn + nt * 8 + 2 * tig;
#pragma unroll
            for (int half = 0; half < 2; half++) {
                int rl = rl0 + half * 8;
                int r  = bm + rl;
                int c  = bn + cl;
                float v0 = acc[mt][nt][2 * half];
                float v1 = acc[mt][nt][2 * half + 1];
                if (MODE == 0) {
                    int idr = idsR_s[rl];
                    v0 = (idr == idsC_s[cl])     ? -1e30f : v0 * scale;
                    v1 = (idr == idsC_s[cl + 1]) ? -1e30f : v1 * scale;
                    float2 o = { v0, v1 };
                    *(float2*)((float*)Cout + (size_t)r * N + c) = o;
                } else if (MODE == 1) {
                    *(__nv_bfloat162*)((__nv_bfloat16*)Cout + (size_t)r * N + c) =
                        __floats2bfloat162_rn(v0, v1);
                } else if (MODE == 2) {
                    v0 += bias_s[cl]; v1 += bias_s[cl + 1];
                    *(__nv_bfloat162*)((__nv_bfloat16*)Cout + (size_t)r * N + c) =
                        __floats2bfloat162_rn(v0, v1);
                } else if (MODE == 3) {
                    __nv_bfloat16* Ct = (__nv_bfloat16*)Cout;
                    Ct[(size_t)c * M + r]       = __float2bfloat16_rn(v0 + bias_s[cl]);
                    Ct[(size_t)(c + 1) * M + r] = __float2bfloat16_rn(v1 + bias_s[cl + 1]);
                } else {
                    const float2 rr = *(const float2*)(resid + (size_t)r * N + c);
                    float2 o = { v0 + bias_s[cl] + rr.x, v1 + bias_s[cl + 1] + rr.y };
                    *(float2*)((float*)Cout + (size_t)r * N + c) = o;
                }
            }
        }
    }
}

// ------------------------- convert / transpose -----------------------------
__global__ __launch_bounds__(256)
void f2b_kernel(const float* __restrict__ in, __nv_bfloat16* __restrict__ out, int n)
{
    int i = (blockIdx.x * 256 + threadIdx.x) * 4;
    if (i < n) {
        float4 v = *(const float4*)&in[i];
        *(__nv_bfloat162*)&out[i]     = __floats2bfloat162_rn(v.x, v.y);
        *(__nv_bfloat162*)&out[i + 2] = __floats2bfloat162_rn(v.z, v.w);
    }
}

// W[K,N] fp32 -> Wt[N,K] bf16
__global__ void wtrans_kernel(const float* __restrict__ W, __nv_bfloat16* __restrict__ Wt,
                              int K, int N)
{
    __shared__ float t[32][33];
    int n0 = blockIdx.x * 32, k0 = blockIdx.y * 32;
    int tx = threadIdx.x, ty = threadIdx.y;   // (32, 8)
#pragma unroll
    for (int i = 0; i < 32; i += 8)
        t[ty + i][tx] = W[(size_t)(k0 + ty + i) * N + n0 + tx];
    __syncthreads();
#pragma unroll
    for (int i = 0; i < 32; i += 8)
        Wt[(size_t)(n0 + ty + i) * K + k0 + tx] = __float2bfloat16_rn(t[tx][ty + i]);
}

// ------------------------------ softmax ------------------------------------
__device__ __forceinline__ float warpMax(float v) {
#pragma unroll
    for (int o = 16; o; o >>= 1) v = fmaxf(v, __shfl_xor_sync(0xFFFFFFFFu, v, o));
    return v;
}
__device__ __forceinline__ float warpSum(float v) {
#pragma unroll
    for (int o = 16; o; o >>= 1) v += __shfl_xor_sync(0xFFFFFFFFu, v, o);
    return v;
}

__global__ __launch_bounds__(512)
void softmax_kernel(const float* __restrict__ S, __nv_bfloat16* __restrict__ P, int N)
{
    __shared__ float buf[NTOK];
    __shared__ float red[16];
    __shared__ float bcast;

    const int row = blockIdx.x;
    const float* Sr = S + (size_t)row * N;
    const int tid = threadIdx.x;
    const int wid = tid >> 5, lid = tid & 31;

    float m = -1e30f;
    for (int i = tid; i < N; i += 512) {
        float v = Sr[i];
        buf[i] = v;
        m = fmaxf(m, v);
    }
    m = warpMax(m);
    if (lid == 0) red[wid] = m;
    __syncthreads();
    if (wid == 0) {
        float v = (lid < 16) ? red[lid] : -1e30f;
        v = warpMax(v);
        if (lid == 0) bcast = v;
    }
    __syncthreads();
    const float rowmax = bcast;

    float s = 0.f;
    for (int i = tid; i < N; i += 512) {
        float e = __expf(buf[i] - rowmax);
        buf[i] = e;
        s += e;
    }
    s = warpSum(s);
    if (lid == 0) red[wid] = s;
    __syncthreads();
    if (wid == 0) {
        float v = (lid < 16) ? red[lid] : 0.f;
        v = warpSum(v);
        if (lid == 0) bcast = v;
    }
    __syncthreads();
    const float inv = 1.f / bcast;

    __nv_bfloat16* Pr = P + (size_t)row * N;
    for (int i = tid * 2; i < N; i += 1024) {
        __nv_bfloat162 p = __floats2bfloat162_rn(buf[i] * inv, buf[i + 1] * inv);
        *(__nv_bfloat162*)&Pr[i] = p;
    }
}

// ------------------------------ layernorm ----------------------------------
__global__ __launch_bounds__(256)
void ln_kernel(const float* __restrict__ H, const float* __restrict__ gamma,
               const float* __restrict__ beta, float* __restrict__ out)
{
    __shared__ float buf[DIM];
    __shared__ float red[8];
    __shared__ float bcast;

    const int row = blockIdx.x;
    const float* Hr = H + (size_t)row * DIM;
    const int tid = threadIdx.x;
    const int wid = tid >> 5, lid = tid & 31;

    float s = 0.f;
    for (int i = tid; i < DIM; i += 256) {
        float v = Hr[i];
        buf[i] = v;
        s += v;
    }
    s = warpSum(s);
    if (lid == 0) red[wid] = s;
    __syncthreads();
    if (wid == 0) {
        float v = (lid < 8) ? red[lid] : 0.f;
        v = warpSum(v);
        if (lid == 0) bcast = v;
    }
    __syncthreads();
    const float mu = bcast * (1.f / DIM);

    float vs = 0.f;
    for (int i = tid; i < DIM; i += 256) {
        float d = buf[i] - mu;
        vs += d * d;
    }
    vs = warpSum(vs);
    if (lid == 0) red[wid] = vs;
    __syncthreads();
    if (wid == 0) {
        float v = (lid < 8) ? red[lid] : 0.f;
        v = warpSum(v);
        if (lid == 0) bcast = v;
    }
    __syncthreads();
    const float rstd = rsqrtf(bcast * (1.f / DIM) + 1e-5f);

    float* Or = out + (size_t)row * DIM;
    for (int i = tid; i < DIM; i += 256)
        Or[i] = (buf[i] - mu) * rstd * gamma[i] + beta[i];
}

// ------------------------------- launch ------------------------------------
extern "C" void kernel_launch(void* const* d_in, const int* in_sizes, int n_in,
                              void* d_out, int out_size)
{
    const float* x     = (const float*)d_in[0];
    const int*   ids   = (const int*)  d_in[1];
    const float* Wq    = (const float*)d_in[2];
    const float* bq    = (const float*)d_in[3];
    const float* Wk    = (const float*)d_in[4];
    const float* bk    = (const float*)d_in[5];
    const float* Wv    = (const float*)d_in[6];
    const float* bv    = (const float*)d_in[7];
    const float* Wo    = (const float*)d_in[8];
    const float* bo    = (const float*)d_in[9];
    const float* gamma = (const float*)d_in[10];
    const float* beta  = (const float*)d_in[11];

    __nv_bfloat16 *xb, *Wqt, *Wkt, *Wvt, *Wot, *Qb, *Kb, *Vt, *Ob, *P;
    float *S, *H;
    cudaGetSymbolAddress((void**)&xb,  g_xb);
    cudaGetSymbolAddress((void**)&Wqt, g_Wqt);
    cudaGetSymbolAddress((void**)&Wkt, g_Wkt);
    cudaGetSymbolAddress((void**)&Wvt, g_Wvt);
    cudaGetSymbolAddress((void**)&Wot, g_Wot);
    cudaGetSymbolAddress((void**)&Qb,  g_Qb);
    cudaGetSymbolAddress((void**)&Kb,  g_Kb);
    cudaGetSymbolAddress((void**)&Vt,  g_Vt);
    cudaGetSymbolAddress((void**)&Ob,  g_Ob);
    cudaGetSymbolAddress((void**)&S,   g_S);
    cudaGetSymbolAddress((void**)&P,   g_P);
    cudaGetSymbolAddress((void**)&H,   g_H);

    // No static guards (harness rule): set attributes unconditionally.
    cudaFuncSetAttribute(gemm_nt<0>, cudaFuncAttributeMaxDynamicSharedMemorySize, SMEM_TOTAL);
    cudaFuncSetAttribute(gemm_nt<1>, cudaFuncAttributeMaxDynamicSharedMemorySize, SMEM_TOTAL);
    cudaFuncSetAttribute(gemm_nt<2>, cudaFuncAttributeMaxDynamicSharedMemorySize, SMEM_TOTAL);
    cudaFuncSetAttribute(gemm_nt<3>, cudaFuncAttributeMaxDynamicSharedMemorySize, SMEM_TOTAL);
    cudaFuncSetAttribute(gemm_nt<4>, cudaFuncAttributeMaxDynamicSharedMemorySize, SMEM_TOTAL);

    const float scale = 0.088388347648318447f;  // 1/sqrt(128)

    // converts
    f2b_kernel<<<(NTOK * DIM) / (256 * 4), 256>>>(x, xb, NTOK * DIM);
    {
        dim3 tb(32, 8), tg(DIM / 32, DIM / 32);
        wtrans_kernel<<<tg, tb>>>(Wq, Wqt, DIM, DIM);
        wtrans_kernel<<<tg, tb>>>(Wk, Wkt, DIM, DIM);
        wtrans_kernel<<<tg, tb>>>(Wv, Wvt, DIM, DIM);
        wtrans_kernel<<<tg, tb>>>(Wo, Wot, DIM, DIM);
    }

    dim3 blk(256);
    dim3 gProj(DIM / BN, NTOK / BM);    // (8, 64)
    dim3 gScore(NTOK / BN, NTOK / BM);  // (64, 64)

    // QKV (as NT against transposed weights)
    gemm_nt<2><<<gProj, blk, SMEM_TOTAL>>>(xb, Wqt, bq, nullptr, nullptr, Qb, NTOK, DIM, DIM, 0.f);
    gemm_nt<2><<<gProj, blk, SMEM_TOTAL>>>(xb, Wkt, bk, nullptr, nullptr, Kb, NTOK, DIM, DIM, 0.f);
    gemm_nt<3><<<gProj, blk, SMEM_TOTAL>>>(xb, Wvt, bv, nullptr, nullptr, Vt, NTOK, DIM, DIM, 0.f);

    // scores + mask
    gemm_nt<0><<<gScore, blk, SMEM_TOTAL>>>(Qb, Kb, nullptr, ids, nullptr, S, NTOK, NTOK, DIM, scale);

    // softmax -> bf16 P
    softmax_kernel<<<NTOK, 512>>>(S, P, NTOK);

    // O = P @ V (Vt rows are K-major over tokens)
    gemm_nt<1><<<gProj, blk, SMEM_TOTAL>>>(P, Vt, nullptr, nullptr, nullptr, Ob, NTOK, DIM, NTOK, 0.f);

    // H = O @ Wo + bo + x
    gemm_nt<4><<<gProj, blk, SMEM_TOTAL>>>(Ob, Wot, bo, nullptr, x, H, NTOK, DIM, DIM, 0.f);

    ln_kernel<<<NTOK, 256>>>(H, gamma, beta, (float*)d_out);
}